// round 16
// baseline (speedup 1.0000x reference)
#include <cuda_runtime.h>
#include <cuda_bf16.h>
#include <math.h>
#include <stdint.h>

#define HID 128
#define MAXN 100000
#define MAXE 1600000
#define SCAN_B 1024

// K-padded bf16 row stride: 136 elements = 272 bytes
#define KS 136
#define KSB 272
#define IMGB (128 * KSB)   // 34816 bytes per [128][136] bf16 image

__device__ float g_h[(size_t)MAXN * HID];
__device__ float g_agg[(size_t)MAXN * HID];
__device__ float g_dinv[MAXN];
__device__ int   g_cnt[MAXN];
__device__ int   g_rowptr[MAXN + 1];
__device__ int   g_cursor[MAXN];
__device__ int   g_partial[(MAXN + SCAN_B - 1) / SCAN_B];
__device__ int   g_eidx[MAXE];
__device__ float g_ew[MAXE];
__device__ __align__(16) unsigned char g_wimg[8 * IMGB];

// ---------------------------------------------------------------------------
__device__ __forceinline__ void mma16816(float* c, uint32_t a0, uint32_t a1,
                                         uint32_t a2, uint32_t a3,
                                         uint32_t b0, uint32_t b1) {
    asm volatile(
        "mma.sync.aligned.m16n8k16.row.col.f32.bf16.bf16.f32 "
        "{%0,%1,%2,%3}, {%4,%5,%6,%7}, {%8,%9}, {%0,%1,%2,%3};"
        : "+f"(c[0]), "+f"(c[1]), "+f"(c[2]), "+f"(c[3])
        : "r"(a0), "r"(a1), "r"(a2), "r"(a3), "r"(b0), "r"(b1));
}

__device__ __forceinline__ void split2(float a, float b, uint32_t& hi, uint32_t& lo) {
    __nv_bfloat16 ha = __float2bfloat16_rn(a), hb = __float2bfloat16_rn(b);
    __nv_bfloat162 H; H.x = ha; H.y = hb;
    __nv_bfloat162 L = __floats2bfloat162_rn(a - __bfloat162float(ha),
                                             b - __bfloat162float(hb));
    hi = *reinterpret_cast<uint32_t*>(&H);
    lo = *reinterpret_cast<uint32_t*>(&L);
}

// ---------------------------------------------------------------------------
// CSR build
// ---------------------------------------------------------------------------
__global__ void cnt_zero_k(int* __restrict__ cnt, int n) {
    int i = blockIdx.x * blockDim.x + threadIdx.x;
    if (i < n) cnt[i] = 0;
}
__global__ void cnt_k(const int* __restrict__ col, int* __restrict__ cnt, int E) {
    int i = blockIdx.x * blockDim.x + threadIdx.x;
    if (i < E) atomicAdd(&cnt[col[i]], 1);
}
__global__ void dinv_k(const int* __restrict__ cnt, float* __restrict__ dinv, int n) {
    int i = blockIdx.x * blockDim.x + threadIdx.x;
    if (i < n) dinv[i] = rsqrtf((float)cnt[i] + 1.f);
}
__global__ __launch_bounds__(SCAN_B) void scan1_k(const int* __restrict__ cnt,
                                                  int* __restrict__ rowptr,
                                                  int* __restrict__ partial, int n) {
    __shared__ int s[SCAN_B];
    int i = blockIdx.x * SCAN_B + threadIdx.x;
    int x = (i < n) ? cnt[i] : 0;
    s[threadIdx.x] = x;
    __syncthreads();
    #pragma unroll
    for (int off = 1; off < SCAN_B; off <<= 1) {
        int v = (threadIdx.x >= off) ? s[threadIdx.x - off] : 0;
        __syncthreads();
        s[threadIdx.x] += v;
        __syncthreads();
    }
    if (i < n) rowptr[i] = s[threadIdx.x] - x;
    if (threadIdx.x == SCAN_B - 1) partial[blockIdx.x] = s[SCAN_B - 1];
}
__global__ __launch_bounds__(SCAN_B) void scan2_k(int* __restrict__ partial, int nparts) {
    __shared__ int s[SCAN_B];
    int t = threadIdx.x;
    int v = (t < nparts) ? partial[t] : 0;
    s[t] = v;
    __syncthreads();
    #pragma unroll
    for (int off = 1; off < SCAN_B; off <<= 1) {
        int u = (t >= off) ? s[t - off] : 0;
        __syncthreads();
        s[t] += u;
        __syncthreads();
    }
    if (t < nparts) partial[t] = s[t] - v;
}
__global__ void scan3_k(int* __restrict__ rowptr, int* __restrict__ cursor,
                        const int* __restrict__ partial, int n, int E) {
    int i = blockIdx.x * blockDim.x + threadIdx.x;
    if (i < n) {
        int v = rowptr[i] + partial[i / SCAN_B];
        rowptr[i] = v;
        cursor[i] = v;
    }
    if (i == 0) rowptr[n] = E;
}
__global__ void place_k(const int* __restrict__ row, const int* __restrict__ col,
                        const float* __restrict__ dinv, int* __restrict__ cursor,
                        int* __restrict__ eidx, float* __restrict__ ew, int E) {
    int e = blockIdx.x * blockDim.x + threadIdx.x;
    if (e >= E) return;
    int r = row[e], c = col[e];
    int p = atomicAdd(&cursor[c], 1);
    eidx[p] = r;
    ew[p] = __ldg(dinv + r) * __ldg(dinv + c);
}

// ---------------------------------------------------------------------------
// W split: W[k][n] fp32 -> BT[n][k] bf16 hi/lo images, stride 136.
// ---------------------------------------------------------------------------
__global__ __launch_bounds__(256) void wsplit_k(const float* __restrict__ W0,
                                                const float* __restrict__ W1,
                                                const float* __restrict__ W2,
                                                const float* __restrict__ W3,
                                                unsigned char* __restrict__ base) {
    const float* src = (blockIdx.x == 0) ? W0 : (blockIdx.x == 1) ? W1
                      : (blockIdx.x == 2) ? W2 : W3;
    unsigned char* dhi = base + (size_t)blockIdx.x * (2 * IMGB);
    unsigned char* dlo = dhi + IMGB;
    for (int i = threadIdx.x; i < 4096; i += 256) {
        int nrow = i >> 5, k4 = i & 31;
        float v0 = src[(4 * k4 + 0) * 128 + nrow];
        float v1 = src[(4 * k4 + 1) * 128 + nrow];
        float v2 = src[(4 * k4 + 2) * 128 + nrow];
        float v3 = src[(4 * k4 + 3) * 128 + nrow];
        uint32_t h0, l0, h1, l1;
        split2(v0, v1, h0, l0);
        split2(v2, v3, h1, l1);
        uint32_t off = (uint32_t)nrow * KSB + 8 * k4;
        *(uint2*)(dhi + off) = make_uint2(h0, h1);
        *(uint2*)(dlo + off) = make_uint2(l0, l1);
    }
    for (int i = threadIdx.x; i < 128; i += 256) {
        *(float4*)(dhi + (uint32_t)i * KSB + 256) = make_float4(0.f, 0.f, 0.f, 0.f);
        *(float4*)(dlo + (uint32_t)i * KSB + 256) = make_float4(0.f, 0.f, 0.f, 0.f);
    }
}

// ---------------------------------------------------------------------------
// Layer GEMM: 512 threads, M-tile 256, warp tile 32x64.
// ---------------------------------------------------------------------------
#define LSM_AHI 0
#define LSM_ALO (256 * KSB)
#define LSM_BHI (2 * 256 * KSB)
#define LSM_BLO (2 * 256 * KSB + IMGB)
#define SMEM_LAYER (2 * 256 * KSB + 2 * IMGB)

template <bool RELU_A>
__global__ __launch_bounds__(512) void mma_layer_k(const float* __restrict__ A,
                                                   const unsigned char* __restrict__ imgHi,
                                                   const unsigned char* __restrict__ imgLo,
                                                   float* __restrict__ C, int n) {
    extern __shared__ unsigned char smem[];
    const int tid = threadIdx.x, lane = tid & 31, wid = tid >> 5;
    const int grp = lane >> 2, tig = lane & 3;
    const int blockM = blockIdx.x * 256;

    for (int i = tid; i < 2176; i += 512) {
        ((float4*)(smem + LSM_BHI))[i] = ((const float4*)imgHi)[i];
        ((float4*)(smem + LSM_BLO))[i] = ((const float4*)imgLo)[i];
    }
    for (int i = tid; i < 8192; i += 512) {
        int m = i >> 5, k4 = i & 31;
        int gm = blockM + m;
        float4 v = make_float4(0.f, 0.f, 0.f, 0.f);
        if (gm < n) v = ((const float4*)A)[(size_t)gm * 32 + k4];
        if (RELU_A) {
            v.x = fmaxf(v.x, 0.f); v.y = fmaxf(v.y, 0.f);
            v.z = fmaxf(v.z, 0.f); v.w = fmaxf(v.w, 0.f);
        }
        uint32_t h0, l0, h1, l1;
        split2(v.x, v.y, h0, l0);
        split2(v.z, v.w, h1, l1);
        uint32_t off = (uint32_t)m * KSB + 8 * k4;
        *(uint2*)(smem + LSM_AHI + off) = make_uint2(h0, h1);
        *(uint2*)(smem + LSM_ALO + off) = make_uint2(l0, l1);
    }
    __syncthreads();

    const int m0 = (wid & 7) * 32;
    const int n0 = (wid >> 3) * 64;

    float acc[2][8][4];
    #pragma unroll
    for (int a = 0; a < 2; a++)
        #pragma unroll
        for (int b = 0; b < 8; b++)
            #pragma unroll
            for (int c = 0; c < 4; c++) acc[a][b][c] = 0.f;

    #pragma unroll
    for (int ks = 0; ks < 8; ks++) {
        const uint32_t kb = ks * 32 + tig * 4;
        uint32_t ah[2][4], al[2][4];
        #pragma unroll
        for (int mt = 0; mt < 2; mt++) {
            uint32_t base = (uint32_t)(m0 + mt * 16 + grp) * KSB + kb;
            ah[mt][0] = *(const uint32_t*)(smem + LSM_AHI + base);
            ah[mt][1] = *(const uint32_t*)(smem + LSM_AHI + base + 8 * KSB);
            ah[mt][2] = *(const uint32_t*)(smem + LSM_AHI + base + 16);
            ah[mt][3] = *(const uint32_t*)(smem + LSM_AHI + base + 8 * KSB + 16);
            al[mt][0] = *(const uint32_t*)(smem + LSM_ALO + base);
            al[mt][1] = *(const uint32_t*)(smem + LSM_ALO + base + 8 * KSB);
            al[mt][2] = *(const uint32_t*)(smem + LSM_ALO + base + 16);
            al[mt][3] = *(const uint32_t*)(smem + LSM_ALO + base + 8 * KSB + 16);
        }
        #pragma unroll
        for (int nt = 0; nt < 8; nt++) {
            uint32_t nb = (uint32_t)(n0 + nt * 8 + grp) * KSB + kb;
            uint32_t bh0 = *(const uint32_t*)(smem + LSM_BHI + nb);
            uint32_t bh1 = *(const uint32_t*)(smem + LSM_BHI + nb + 16);
            uint32_t bl0 = *(const uint32_t*)(smem + LSM_BLO + nb);
            uint32_t bl1 = *(const uint32_t*)(smem + LSM_BLO + nb + 16);
            #pragma unroll
            for (int mt = 0; mt < 2; mt++) {
                mma16816(acc[mt][nt], ah[mt][0], ah[mt][1], ah[mt][2], ah[mt][3], bh0, bh1);
                mma16816(acc[mt][nt], ah[mt][0], ah[mt][1], ah[mt][2], ah[mt][3], bl0, bl1);
                mma16816(acc[mt][nt], al[mt][0], al[mt][1], al[mt][2], al[mt][3], bh0, bh1);
            }
        }
    }

    #pragma unroll
    for (int mt = 0; mt < 2; mt++) {
        int row = m0 + mt * 16 + grp;
        #pragma unroll
        for (int nt = 0; nt < 8; nt++) {
            int col = n0 + nt * 8 + tig * 2;
            int gm = blockM + row;
            if (gm < n)
                *(float2*)(C + (size_t)gm * 128 + col) =
                    make_float2(acc[mt][nt][0], acc[mt][nt][1]);
            if (gm + 8 < n)
                *(float2*)(C + (size_t)(gm + 8) * 128 + col) =
                    make_float2(acc[mt][nt][2], acc[mt][nt][3]);
        }
    }
}

// ---------------------------------------------------------------------------
// Head kernel (R7 form: pp-dot via a final global re-read of A).
// ---------------------------------------------------------------------------
#define HSM_AHI 0
#define HSM_ALO IMGB
#define HSM_B   (2 * IMGB)
#define HSM_VEC (6 * IMGB)
#define SMEM_HEAD (6 * IMGB + 7 * 512)

__global__ __launch_bounds__(512) void mma_head_k(
    const float* __restrict__ A, const unsigned char* __restrict__ imgs,
    const float* __restrict__ b00L, const float* __restrict__ b10L,
    const float* __restrict__ w01, const float* __restrict__ b01,
    const float* __restrict__ w11, const float* __restrict__ b11,
    const float* __restrict__ ppw, const float* __restrict__ ppb,
    const int* __restrict__ t, float* __restrict__ out, int n) {
    extern __shared__ unsigned char smem[];
    const int tid = threadIdx.x, lane = tid & 31, wid = tid >> 5;
    const int grp = lane >> 2, tig = lane & 3;
    const int blockM = blockIdx.x * 128;

    float* ppws = (float*)(smem + HSM_VEC);
    float* b0s  = ppws + 128;
    float* b1s  = b0s + 128;
    float* w01s = b1s + 128;
    float* w11s = w01s + 128;
    float* y0s  = w11s + 128;
    float* y1s  = y0s + 128;

    if (tid < 128) {
        ppws[tid] = ppw[tid];
        b0s[tid]  = b00L[tid];
        b1s[tid]  = b10L[tid];
        w01s[tid] = w01[tid];
        w11s[tid] = w11[tid];
        y0s[tid]  = 0.f;
        y1s[tid]  = 0.f;
    }
    for (int i = tid; i < 8704; i += 512)
        ((float4*)(smem + HSM_B))[i] = ((const float4*)imgs)[i];
    for (int i = tid; i < 4096; i += 512) {
        int m = i >> 5, k4 = i & 31;
        int gm = blockM + m;
        float4 v = make_float4(0.f, 0.f, 0.f, 0.f);
        if (gm < n) v = ((const float4*)A)[(size_t)gm * 32 + k4];
        v.x = fmaxf(v.x, 0.f); v.y = fmaxf(v.y, 0.f);
        v.z = fmaxf(v.z, 0.f); v.w = fmaxf(v.w, 0.f);
        uint32_t h0, l0, h1, l1;
        split2(v.x, v.y, h0, l0);
        split2(v.z, v.w, h1, l1);
        uint32_t off = (uint32_t)m * KSB + 8 * k4;
        *(uint2*)(smem + HSM_AHI + off) = make_uint2(h0, h1);
        *(uint2*)(smem + HSM_ALO + off) = make_uint2(l0, l1);
    }
    __syncthreads();

    const int m0 = (wid & 3) * 32;
    const int nblk = wid >> 2;
    const int head = nblk >> 1;
    const uint32_t bHi = HSM_B + head * (2 * IMGB);
    const uint32_t bLo = bHi + IMGB;
    const int ncol0 = (nblk & 1) * 64;

    float acc[2][8][4];
    #pragma unroll
    for (int a = 0; a < 2; a++)
        #pragma unroll
        for (int b = 0; b < 8; b++)
            #pragma unroll
            for (int c = 0; c < 4; c++) acc[a][b][c] = 0.f;

    #pragma unroll
    for (int ks = 0; ks < 8; ks++) {
        const uint32_t kb = ks * 32 + tig * 4;
        uint32_t ah[2][4], al[2][4];
        #pragma unroll
        for (int mt = 0; mt < 2; mt++) {
            uint32_t base = (uint32_t)(m0 + mt * 16 + grp) * KSB + kb;
            ah[mt][0] = *(const uint32_t*)(smem + HSM_AHI + base);
            ah[mt][1] = *(const uint32_t*)(smem + HSM_AHI + base + 8 * KSB);
            ah[mt][2] = *(const uint32_t*)(smem + HSM_AHI + base + 16);
            ah[mt][3] = *(const uint32_t*)(smem + HSM_AHI + base + 8 * KSB + 16);
            al[mt][0] = *(const uint32_t*)(smem + HSM_ALO + base);
            al[mt][1] = *(const uint32_t*)(smem + HSM_ALO + base + 8 * KSB);
            al[mt][2] = *(const uint32_t*)(smem + HSM_ALO + base + 16);
            al[mt][3] = *(const uint32_t*)(smem + HSM_ALO + base + 8 * KSB + 16);
        }
        #pragma unroll
        for (int nt = 0; nt < 8; nt++) {
            uint32_t nb = (uint32_t)(ncol0 + nt * 8 + grp) * KSB + kb;
            uint32_t bh0 = *(const uint32_t*)(smem + bHi + nb);
            uint32_t bh1 = *(const uint32_t*)(smem + bHi + nb + 16);
            uint32_t bl0 = *(const uint32_t*)(smem + bLo + nb);
            uint32_t bl1 = *(const uint32_t*)(smem + bLo + nb + 16);
            #pragma unroll
            for (int mt = 0; mt < 2; mt++) {
                mma16816(acc[mt][nt], ah[mt][0], ah[mt][1], ah[mt][2], ah[mt][3], bh0, bh1);
                mma16816(acc[mt][nt], ah[mt][0], ah[mt][1], ah[mt][2], ah[mt][3], bl0, bl1);
                mma16816(acc[mt][nt], al[mt][0], al[mt][1], al[mt][2], al[mt][3], bh0, bh1);
            }
        }
    }

    const float* bs = head ? b1s : b0s;
    const float* ws = head ? w11s : w01s;
    float* ys = head ? y1s : y0s;
    #pragma unroll
    for (int mt = 0; mt < 2; mt++) {
        float p0 = 0.f, p1 = 0.f;
        #pragma unroll
        for (int nt = 0; nt < 8; nt++) {
            int col = ncol0 + nt * 8 + tig * 2;
            p0 += fmaxf(acc[mt][nt][0] + bs[col], 0.f) * ws[col]
                + fmaxf(acc[mt][nt][1] + bs[col + 1], 0.f) * ws[col + 1];
            p1 += fmaxf(acc[mt][nt][2] + bs[col], 0.f) * ws[col]
                + fmaxf(acc[mt][nt][3] + bs[col + 1], 0.f) * ws[col + 1];
        }
        p0 += __shfl_xor_sync(0xffffffffu, p0, 1);
        p0 += __shfl_xor_sync(0xffffffffu, p0, 2);
        p1 += __shfl_xor_sync(0xffffffffu, p1, 1);
        p1 += __shfl_xor_sync(0xffffffffu, p1, 2);
        if (tig == 0) {
            atomicAdd(&ys[m0 + mt * 16 + grp], p0);
            atomicAdd(&ys[m0 + mt * 16 + grp + 8], p1);
        }
    }
    __syncthreads();

    if (tid < 128) {
        int gm = blockM + tid;
        if (gm < n) {
            float pp = 0.f;
            const float4* a4 = (const float4*)A + (size_t)gm * 32;
            #pragma unroll 8
            for (int k4 = 0; k4 < 32; k4++) {
                float4 v = a4[k4];
                pp += fmaxf(v.x, 0.f) * ppws[4 * k4]
                    + fmaxf(v.y, 0.f) * ppws[4 * k4 + 1]
                    + fmaxf(v.z, 0.f) * ppws[4 * k4 + 2]
                    + fmaxf(v.w, 0.f) * ppws[4 * k4 + 3];
            }
            out[gm] = 1.f / (1.f + expf(-(pp + ppb[0])));
            out[n + gm] = (t[gm] > 0) ? (y1s[tid] + b11[0]) : (y0s[tid] + b01[0]);
        }
    }
}

// ---------------------------------------------------------------------------
// CSR gather v2: TWO warps per node (feature-dim split). Warp handles one
// 256B half-row; lane owns a float2. Same bytes, 2x warp-level parallelism,
// lower per-warp register pressure than any wider unroll.
// ---------------------------------------------------------------------------
__global__ __launch_bounds__(256) void gather_k(const float* __restrict__ h,
                                                const int* __restrict__ rowptr,
                                                const int* __restrict__ eidx,
                                                const float* __restrict__ ew,
                                                const float* __restrict__ dinv,
                                                const float* __restrict__ b,
                                                float* __restrict__ agg, int n) {
    const int lane = threadIdx.x & 31;
    const int gw = (blockIdx.x * blockDim.x + threadIdx.x) >> 5;
    const int node = gw >> 1;
    const int half = gw & 1;
    if (node >= n) return;

    const float2* h2 = (const float2*)h;
    const int fo = half * 32 + lane;           // float2 index within the 64-wide row
    float d = __ldg(dinv + node);
    float d2 = d * d;

    float2 sv = h2[(size_t)node * 64 + fo];
    float2 bb = ((const float2*)b)[fo];
    float2 a0, a1, a2, a3;
    a0.x = fmaf(sv.x, d2, bb.x); a0.y = fmaf(sv.y, d2, bb.y);
    a1 = make_float2(0.f, 0.f);
    a2 = make_float2(0.f, 0.f);
    a3 = make_float2(0.f, 0.f);

    int e = __ldg(rowptr + node);
    const int end = __ldg(rowptr + node + 1);
    for (; e + 3 < end; e += 4) {
        int r0 = __ldg(eidx + e),     r1 = __ldg(eidx + e + 1);
        int r2 = __ldg(eidx + e + 2), r3 = __ldg(eidx + e + 3);
        float w0 = __ldg(ew + e),     w1 = __ldg(ew + e + 1);
        float w2 = __ldg(ew + e + 2), w3 = __ldg(ew + e + 3);
        float2 v0 = h2[(size_t)r0 * 64 + fo];
        float2 v1 = h2[(size_t)r1 * 64 + fo];
        float2 v2 = h2[(size_t)r2 * 64 + fo];
        float2 v3 = h2[(size_t)r3 * 64 + fo];
        a0.x = fmaf(v0.x, w0, a0.x); a0.y = fmaf(v0.y, w0, a0.y);
        a1.x = fmaf(v1.x, w1, a1.x); a1.y = fmaf(v1.y, w1, a1.y);
        a2.x = fmaf(v2.x, w2, a2.x); a2.y = fmaf(v2.y, w2, a2.y);
        a3.x = fmaf(v3.x, w3, a3.x); a3.y = fmaf(v3.y, w3, a3.y);
    }
    for (; e < end; e++) {
        int r0 = __ldg(eidx + e);
        float w0 = __ldg(ew + e);
        float2 v0 = h2[(size_t)r0 * 64 + fo];
        a0.x = fmaf(v0.x, w0, a0.x); a0.y = fmaf(v0.y, w0, a0.y);
    }
    a0.x += a1.x + a2.x + a3.x;
    a0.y += a1.y + a2.y + a3.y;
    ((float2*)agg)[(size_t)node * 64 + fo] = a0;
}

// ---------------------------------------------------------------------------
extern "C" void kernel_launch(void* const* d_in, const int* in_sizes, int n_in,
                              void* d_out, int out_size) {
    const float* x   = (const float*)d_in[0];
    const int*   t   = (const int*)d_in[1];
    const int*   ei  = (const int*)d_in[3];
    const float* W0  = (const float*)d_in[4];
    const float* b0  = (const float*)d_in[5];
    const float* W1  = (const float*)d_in[6];
    const float* b1  = (const float*)d_in[7];
    const float* W00 = (const float*)d_in[8];
    const float* b00 = (const float*)d_in[9];
    const float* W10 = (const float*)d_in[10];
    const float* b10 = (const float*)d_in[11];
    const float* w01 = (const float*)d_in[12];
    const float* b01 = (const float*)d_in[13];
    const float* w11 = (const float*)d_in[14];
    const float* b11 = (const float*)d_in[15];
    const float* ppw = (const float*)d_in[16];
    const float* ppb = (const float*)d_in[17];
    float* out = (float*)d_out;

    const int N = in_sizes[0] / HID;
    const int E = in_sizes[3] / 2;
    const int* row = ei;
    const int* col = ei + E;

    float *h, *agg, *dinv, *ew;
    int *cnt, *rowptr, *cursor, *partial, *eidx;
    unsigned char* wimg;
    cudaGetSymbolAddress((void**)&h, g_h);
    cudaGetSymbolAddress((void**)&agg, g_agg);
    cudaGetSymbolAddress((void**)&dinv, g_dinv);
    cudaGetSymbolAddress((void**)&cnt, g_cnt);
    cudaGetSymbolAddress((void**)&rowptr, g_rowptr);
    cudaGetSymbolAddress((void**)&cursor, g_cursor);
    cudaGetSymbolAddress((void**)&partial, g_partial);
    cudaGetSymbolAddress((void**)&eidx, g_eidx);
    cudaGetSymbolAddress((void**)&ew, g_ew);
    cudaGetSymbolAddress((void**)&wimg, g_wimg);

    cudaFuncSetAttribute((const void*)mma_layer_k<false>,
                         cudaFuncAttributeMaxDynamicSharedMemorySize, SMEM_LAYER);
    cudaFuncSetAttribute((const void*)mma_layer_k<true>,
                         cudaFuncAttributeMaxDynamicSharedMemorySize, SMEM_LAYER);
    cudaFuncSetAttribute((const void*)mma_head_k,
                         cudaFuncAttributeMaxDynamicSharedMemorySize, SMEM_HEAD);

    const int nparts = (N + SCAN_B - 1) / SCAN_B;
    const int gb256 = (N + 255) / 256;
    const int gb128 = (N + 127) / 128;
    const int gg = (N * 64 + 255) / 256;   // 2 warps per node

    cnt_zero_k<<<(N + 255) / 256, 256>>>(cnt, N);
    cnt_k<<<(E + 255) / 256, 256>>>(col, cnt, E);
    dinv_k<<<(N + 255) / 256, 256>>>(cnt, dinv, N);
    scan1_k<<<nparts, SCAN_B>>>(cnt, rowptr, partial, N);
    wsplit_k<<<4, 256>>>(W0, W1, W00 + 128 * 128, W10 + 128 * 128, wimg);
    mma_layer_k<false><<<gb256, 512, SMEM_LAYER>>>(x, wimg, wimg + IMGB, h, N);
    scan2_k<<<1, SCAN_B>>>(partial, nparts);
    scan3_k<<<(N + 255) / 256, 256>>>(rowptr, cursor, partial, N, E);
    place_k<<<(E + 255) / 256, 256>>>(row, col, dinv, cursor, eidx, ew, E);

    // layer 1 aggregation
    gather_k<<<gg, 256>>>(h, rowptr, eidx, ew, dinv, b0, agg, N);

    // layer 2
    mma_layer_k<true><<<gb256, 512, SMEM_LAYER>>>(agg, wimg + 2 * IMGB, wimg + 3 * IMGB, h, N);
    gather_k<<<gg, 256>>>(h, rowptr, eidx, ew, dinv, b1, agg, N);

    // fused heads
    mma_head_k<<<gb128, 512, SMEM_HEAD>>>(agg, wimg + 4 * IMGB,
                                          b00 + 128, b10 + 128,
                                          w01, b01, w11, b11, ppw, ppb, t, out, N);
}

// round 17
// speedup vs baseline: 1.0663x; 1.0663x over previous
#include <cuda_runtime.h>
#include <cuda_bf16.h>
#include <math.h>
#include <stdint.h>

#define HID 128
#define MAXN 100000
#define MAXE 1600000
#define SCAN_B 1024

// K-padded bf16 row stride: 136 elements = 272 bytes
#define KS 136
#define KSB 272
#define IMGB (128 * KSB)   // 34816 bytes per [128][136] bf16 image

__device__ float g_h[(size_t)MAXN * HID];
__device__ float g_agg[(size_t)MAXN * HID];
__device__ float g_dinv[MAXN];
__device__ int   g_cnt[MAXN];
__device__ int   g_rowptr[MAXN + 1];
__device__ int   g_cursor[MAXN];
__device__ int   g_partial[(MAXN + SCAN_B - 1) / SCAN_B];
__device__ int   g_eidx[MAXE];
__device__ float g_ew[MAXE];
__device__ __align__(16) unsigned char g_wimg[8 * IMGB];

// ---------------------------------------------------------------------------
__device__ __forceinline__ void mma16816(float* c, uint32_t a0, uint32_t a1,
                                         uint32_t a2, uint32_t a3,
                                         uint32_t b0, uint32_t b1) {
    asm volatile(
        "mma.sync.aligned.m16n8k16.row.col.f32.bf16.bf16.f32 "
        "{%0,%1,%2,%3}, {%4,%5,%6,%7}, {%8,%9}, {%0,%1,%2,%3};"
        : "+f"(c[0]), "+f"(c[1]), "+f"(c[2]), "+f"(c[3])
        : "r"(a0), "r"(a1), "r"(a2), "r"(a3), "r"(b0), "r"(b1));
}

__device__ __forceinline__ void split2(float a, float b, uint32_t& hi, uint32_t& lo) {
    __nv_bfloat16 ha = __float2bfloat16_rn(a), hb = __float2bfloat16_rn(b);
    __nv_bfloat162 H; H.x = ha; H.y = hb;
    __nv_bfloat162 L = __floats2bfloat162_rn(a - __bfloat162float(ha),
                                             b - __bfloat162float(hb));
    hi = *reinterpret_cast<uint32_t*>(&H);
    lo = *reinterpret_cast<uint32_t*>(&L);
}

// ---------------------------------------------------------------------------
// CSR build
// ---------------------------------------------------------------------------
__global__ void cnt_zero_k(int* __restrict__ cnt, int n) {
    int i = blockIdx.x * blockDim.x + threadIdx.x;
    if (i < n) cnt[i] = 0;
}
__global__ void cnt_k(const int* __restrict__ col, int* __restrict__ cnt, int E) {
    int i = blockIdx.x * blockDim.x + threadIdx.x;
    if (i < E) atomicAdd(&cnt[col[i]], 1);
}
__global__ void dinv_k(const int* __restrict__ cnt, float* __restrict__ dinv, int n) {
    int i = blockIdx.x * blockDim.x + threadIdx.x;
    if (i < n) dinv[i] = rsqrtf((float)cnt[i] + 1.f);
}
__global__ __launch_bounds__(SCAN_B) void scan1_k(const int* __restrict__ cnt,
                                                  int* __restrict__ rowptr,
                                                  int* __restrict__ partial, int n) {
    __shared__ int s[SCAN_B];
    int i = blockIdx.x * SCAN_B + threadIdx.x;
    int x = (i < n) ? cnt[i] : 0;
    s[threadIdx.x] = x;
    __syncthreads();
    #pragma unroll
    for (int off = 1; off < SCAN_B; off <<= 1) {
        int v = (threadIdx.x >= off) ? s[threadIdx.x - off] : 0;
        __syncthreads();
        s[threadIdx.x] += v;
        __syncthreads();
    }
    if (i < n) rowptr[i] = s[threadIdx.x] - x;
    if (threadIdx.x == SCAN_B - 1) partial[blockIdx.x] = s[SCAN_B - 1];
}
__global__ __launch_bounds__(SCAN_B) void scan2_k(int* __restrict__ partial, int nparts) {
    __shared__ int s[SCAN_B];
    int t = threadIdx.x;
    int v = (t < nparts) ? partial[t] : 0;
    s[t] = v;
    __syncthreads();
    #pragma unroll
    for (int off = 1; off < SCAN_B; off <<= 1) {
        int u = (t >= off) ? s[t - off] : 0;
        __syncthreads();
        s[t] += u;
        __syncthreads();
    }
    if (t < nparts) partial[t] = s[t] - v;
}
__global__ void scan3_k(int* __restrict__ rowptr, int* __restrict__ cursor,
                        const int* __restrict__ partial, int n, int E) {
    int i = blockIdx.x * blockDim.x + threadIdx.x;
    if (i < n) {
        int v = rowptr[i] + partial[i / SCAN_B];
        rowptr[i] = v;
        cursor[i] = v;
    }
    if (i == 0) rowptr[n] = E;
}
__global__ void place_k(const int* __restrict__ row, const int* __restrict__ col,
                        const float* __restrict__ dinv, int* __restrict__ cursor,
                        int* __restrict__ eidx, float* __restrict__ ew, int E) {
    int e = blockIdx.x * blockDim.x + threadIdx.x;
    if (e >= E) return;
    int r = row[e], c = col[e];
    int p = atomicAdd(&cursor[c], 1);
    eidx[p] = r;
    ew[p] = __ldg(dinv + r) * __ldg(dinv + c);
}

// ---------------------------------------------------------------------------
// W split: W[k][n] fp32 -> BT[n][k] bf16 hi/lo images, stride 136.
// ---------------------------------------------------------------------------
__global__ __launch_bounds__(256) void wsplit_k(const float* __restrict__ W0,
                                                const float* __restrict__ W1,
                                                const float* __restrict__ W2,
                                                const float* __restrict__ W3,
                                                unsigned char* __restrict__ base) {
    const float* src = (blockIdx.x == 0) ? W0 : (blockIdx.x == 1) ? W1
                      : (blockIdx.x == 2) ? W2 : W3;
    unsigned char* dhi = base + (size_t)blockIdx.x * (2 * IMGB);
    unsigned char* dlo = dhi + IMGB;
    for (int i = threadIdx.x; i < 4096; i += 256) {
        int nrow = i >> 5, k4 = i & 31;
        float v0 = src[(4 * k4 + 0) * 128 + nrow];
        float v1 = src[(4 * k4 + 1) * 128 + nrow];
        float v2 = src[(4 * k4 + 2) * 128 + nrow];
        float v3 = src[(4 * k4 + 3) * 128 + nrow];
        uint32_t h0, l0, h1, l1;
        split2(v0, v1, h0, l0);
        split2(v2, v3, h1, l1);
        uint32_t off = (uint32_t)nrow * KSB + 8 * k4;
        *(uint2*)(dhi + off) = make_uint2(h0, h1);
        *(uint2*)(dlo + off) = make_uint2(l0, l1);
    }
    for (int i = threadIdx.x; i < 128; i += 256) {
        *(float4*)(dhi + (uint32_t)i * KSB + 256) = make_float4(0.f, 0.f, 0.f, 0.f);
        *(float4*)(dlo + (uint32_t)i * KSB + 256) = make_float4(0.f, 0.f, 0.f, 0.f);
    }
}

// ---------------------------------------------------------------------------
// Layer GEMM: 512 threads, M-tile 256, warp tile 32x64.
// ---------------------------------------------------------------------------
#define LSM_AHI 0
#define LSM_ALO (256 * KSB)
#define LSM_BHI (2 * 256 * KSB)
#define LSM_BLO (2 * 256 * KSB + IMGB)
#define SMEM_LAYER (2 * 256 * KSB + 2 * IMGB)

template <bool RELU_A>
__global__ __launch_bounds__(512) void mma_layer_k(const float* __restrict__ A,
                                                   const unsigned char* __restrict__ imgHi,
                                                   const unsigned char* __restrict__ imgLo,
                                                   float* __restrict__ C, int n) {
    extern __shared__ unsigned char smem[];
    const int tid = threadIdx.x, lane = tid & 31, wid = tid >> 5;
    const int grp = lane >> 2, tig = lane & 3;
    const int blockM = blockIdx.x * 256;

    for (int i = tid; i < 2176; i += 512) {
        ((float4*)(smem + LSM_BHI))[i] = ((const float4*)imgHi)[i];
        ((float4*)(smem + LSM_BLO))[i] = ((const float4*)imgLo)[i];
    }
    for (int i = tid; i < 8192; i += 512) {
        int m = i >> 5, k4 = i & 31;
        int gm = blockM + m;
        float4 v = make_float4(0.f, 0.f, 0.f, 0.f);
        if (gm < n) v = ((const float4*)A)[(size_t)gm * 32 + k4];
        if (RELU_A) {
            v.x = fmaxf(v.x, 0.f); v.y = fmaxf(v.y, 0.f);
            v.z = fmaxf(v.z, 0.f); v.w = fmaxf(v.w, 0.f);
        }
        uint32_t h0, l0, h1, l1;
        split2(v.x, v.y, h0, l0);
        split2(v.z, v.w, h1, l1);
        uint32_t off = (uint32_t)m * KSB + 8 * k4;
        *(uint2*)(smem + LSM_AHI + off) = make_uint2(h0, h1);
        *(uint2*)(smem + LSM_ALO + off) = make_uint2(l0, l1);
    }
    __syncthreads();

    const int m0 = (wid & 7) * 32;
    const int n0 = (wid >> 3) * 64;

    float acc[2][8][4];
    #pragma unroll
    for (int a = 0; a < 2; a++)
        #pragma unroll
        for (int b = 0; b < 8; b++)
            #pragma unroll
            for (int c = 0; c < 4; c++) acc[a][b][c] = 0.f;

    #pragma unroll
    for (int ks = 0; ks < 8; ks++) {
        const uint32_t kb = ks * 32 + tig * 4;
        uint32_t ah[2][4], al[2][4];
        #pragma unroll
        for (int mt = 0; mt < 2; mt++) {
            uint32_t base = (uint32_t)(m0 + mt * 16 + grp) * KSB + kb;
            ah[mt][0] = *(const uint32_t*)(smem + LSM_AHI + base);
            ah[mt][1] = *(const uint32_t*)(smem + LSM_AHI + base + 8 * KSB);
            ah[mt][2] = *(const uint32_t*)(smem + LSM_AHI + base + 16);
            ah[mt][3] = *(const uint32_t*)(smem + LSM_AHI + base + 8 * KSB + 16);
            al[mt][0] = *(const uint32_t*)(smem + LSM_ALO + base);
            al[mt][1] = *(const uint32_t*)(smem + LSM_ALO + base + 8 * KSB);
            al[mt][2] = *(const uint32_t*)(smem + LSM_ALO + base + 16);
            al[mt][3] = *(const uint32_t*)(smem + LSM_ALO + base + 8 * KSB + 16);
        }
        #pragma unroll
        for (int nt = 0; nt < 8; nt++) {
            uint32_t nb = (uint32_t)(n0 + nt * 8 + grp) * KSB + kb;
            uint32_t bh0 = *(const uint32_t*)(smem + LSM_BHI + nb);
            uint32_t bh1 = *(const uint32_t*)(smem + LSM_BHI + nb + 16);
            uint32_t bl0 = *(const uint32_t*)(smem + LSM_BLO + nb);
            uint32_t bl1 = *(const uint32_t*)(smem + LSM_BLO + nb + 16);
            #pragma unroll
            for (int mt = 0; mt < 2; mt++) {
                mma16816(acc[mt][nt], ah[mt][0], ah[mt][1], ah[mt][2], ah[mt][3], bh0, bh1);
                mma16816(acc[mt][nt], ah[mt][0], ah[mt][1], ah[mt][2], ah[mt][3], bl0, bl1);
                mma16816(acc[mt][nt], al[mt][0], al[mt][1], al[mt][2], al[mt][3], bh0, bh1);
            }
        }
    }

    #pragma unroll
    for (int mt = 0; mt < 2; mt++) {
        int row = m0 + mt * 16 + grp;
        #pragma unroll
        for (int nt = 0; nt < 8; nt++) {
            int col = n0 + nt * 8 + tig * 2;
            int gm = blockM + row;
            if (gm < n)
                *(float2*)(C + (size_t)gm * 128 + col) =
                    make_float2(acc[mt][nt][0], acc[mt][nt][1]);
            if (gm + 8 < n)
                *(float2*)(C + (size_t)(gm + 8) * 128 + col) =
                    make_float2(acc[mt][nt][2], acc[mt][nt][3]);
        }
    }
}

// ---------------------------------------------------------------------------
// Head kernel (R7 form: pp-dot via a final global re-read of A).
// ---------------------------------------------------------------------------
#define HSM_AHI 0
#define HSM_ALO IMGB
#define HSM_B   (2 * IMGB)
#define HSM_VEC (6 * IMGB)
#define SMEM_HEAD (6 * IMGB + 7 * 512)

__global__ __launch_bounds__(512) void mma_head_k(
    const float* __restrict__ A, const unsigned char* __restrict__ imgs,
    const float* __restrict__ b00L, const float* __restrict__ b10L,
    const float* __restrict__ w01, const float* __restrict__ b01,
    const float* __restrict__ w11, const float* __restrict__ b11,
    const float* __restrict__ ppw, const float* __restrict__ ppb,
    const int* __restrict__ t, float* __restrict__ out, int n) {
    extern __shared__ unsigned char smem[];
    const int tid = threadIdx.x, lane = tid & 31, wid = tid >> 5;
    const int grp = lane >> 2, tig = lane & 3;
    const int blockM = blockIdx.x * 128;

    float* ppws = (float*)(smem + HSM_VEC);
    float* b0s  = ppws + 128;
    float* b1s  = b0s + 128;
    float* w01s = b1s + 128;
    float* w11s = w01s + 128;
    float* y0s  = w11s + 128;
    float* y1s  = y0s + 128;

    if (tid < 128) {
        ppws[tid] = ppw[tid];
        b0s[tid]  = b00L[tid];
        b1s[tid]  = b10L[tid];
        w01s[tid] = w01[tid];
        w11s[tid] = w11[tid];
        y0s[tid]  = 0.f;
        y1s[tid]  = 0.f;
    }
    for (int i = tid; i < 8704; i += 512)
        ((float4*)(smem + HSM_B))[i] = ((const float4*)imgs)[i];
    for (int i = tid; i < 4096; i += 512) {
        int m = i >> 5, k4 = i & 31;
        int gm = blockM + m;
        float4 v = make_float4(0.f, 0.f, 0.f, 0.f);
        if (gm < n) v = ((const float4*)A)[(size_t)gm * 32 + k4];
        v.x = fmaxf(v.x, 0.f); v.y = fmaxf(v.y, 0.f);
        v.z = fmaxf(v.z, 0.f); v.w = fmaxf(v.w, 0.f);
        uint32_t h0, l0, h1, l1;
        split2(v.x, v.y, h0, l0);
        split2(v.z, v.w, h1, l1);
        uint32_t off = (uint32_t)m * KSB + 8 * k4;
        *(uint2*)(smem + HSM_AHI + off) = make_uint2(h0, h1);
        *(uint2*)(smem + HSM_ALO + off) = make_uint2(l0, l1);
    }
    __syncthreads();

    const int m0 = (wid & 3) * 32;
    const int nblk = wid >> 2;
    const int head = nblk >> 1;
    const uint32_t bHi = HSM_B + head * (2 * IMGB);
    const uint32_t bLo = bHi + IMGB;
    const int ncol0 = (nblk & 1) * 64;

    float acc[2][8][4];
    #pragma unroll
    for (int a = 0; a < 2; a++)
        #pragma unroll
        for (int b = 0; b < 8; b++)
            #pragma unroll
            for (int c = 0; c < 4; c++) acc[a][b][c] = 0.f;

    #pragma unroll
    for (int ks = 0; ks < 8; ks++) {
        const uint32_t kb = ks * 32 + tig * 4;
        uint32_t ah[2][4], al[2][4];
        #pragma unroll
        for (int mt = 0; mt < 2; mt++) {
            uint32_t base = (uint32_t)(m0 + mt * 16 + grp) * KSB + kb;
            ah[mt][0] = *(const uint32_t*)(smem + HSM_AHI + base);
            ah[mt][1] = *(const uint32_t*)(smem + HSM_AHI + base + 8 * KSB);
            ah[mt][2] = *(const uint32_t*)(smem + HSM_AHI + base + 16);
            ah[mt][3] = *(const uint32_t*)(smem + HSM_AHI + base + 8 * KSB + 16);
            al[mt][0] = *(const uint32_t*)(smem + HSM_ALO + base);
            al[mt][1] = *(const uint32_t*)(smem + HSM_ALO + base + 8 * KSB);
            al[mt][2] = *(const uint32_t*)(smem + HSM_ALO + base + 16);
            al[mt][3] = *(const uint32_t*)(smem + HSM_ALO + base + 8 * KSB + 16);
        }
        #pragma unroll
        for (int nt = 0; nt < 8; nt++) {
            uint32_t nb = (uint32_t)(ncol0 + nt * 8 + grp) * KSB + kb;
            uint32_t bh0 = *(const uint32_t*)(smem + bHi + nb);
            uint32_t bh1 = *(const uint32_t*)(smem + bHi + nb + 16);
            uint32_t bl0 = *(const uint32_t*)(smem + bLo + nb);
            uint32_t bl1 = *(const uint32_t*)(smem + bLo + nb + 16);
            #pragma unroll
            for (int mt = 0; mt < 2; mt++) {
                mma16816(acc[mt][nt], ah[mt][0], ah[mt][1], ah[mt][2], ah[mt][3], bh0, bh1);
                mma16816(acc[mt][nt], ah[mt][0], ah[mt][1], ah[mt][2], ah[mt][3], bl0, bl1);
                mma16816(acc[mt][nt], al[mt][0], al[mt][1], al[mt][2], al[mt][3], bh0, bh1);
            }
        }
    }

    const float* bs = head ? b1s : b0s;
    const float* ws = head ? w11s : w01s;
    float* ys = head ? y1s : y0s;
    #pragma unroll
    for (int mt = 0; mt < 2; mt++) {
        float p0 = 0.f, p1 = 0.f;
        #pragma unroll
        for (int nt = 0; nt < 8; nt++) {
            int col = ncol0 + nt * 8 + tig * 2;
            p0 += fmaxf(acc[mt][nt][0] + bs[col], 0.f) * ws[col]
                + fmaxf(acc[mt][nt][1] + bs[col + 1], 0.f) * ws[col + 1];
            p1 += fmaxf(acc[mt][nt][2] + bs[col], 0.f) * ws[col]
                + fmaxf(acc[mt][nt][3] + bs[col + 1], 0.f) * ws[col + 1];
        }
        p0 += __shfl_xor_sync(0xffffffffu, p0, 1);
        p0 += __shfl_xor_sync(0xffffffffu, p0, 2);
        p1 += __shfl_xor_sync(0xffffffffu, p1, 1);
        p1 += __shfl_xor_sync(0xffffffffu, p1, 2);
        if (tig == 0) {
            atomicAdd(&ys[m0 + mt * 16 + grp], p0);
            atomicAdd(&ys[m0 + mt * 16 + grp + 8], p1);
        }
    }
    __syncthreads();

    if (tid < 128) {
        int gm = blockM + tid;
        if (gm < n) {
            float pp = 0.f;
            const float4* a4 = (const float4*)A + (size_t)gm * 32;
            #pragma unroll 8
            for (int k4 = 0; k4 < 32; k4++) {
                float4 v = a4[k4];
                pp += fmaxf(v.x, 0.f) * ppws[4 * k4]
                    + fmaxf(v.y, 0.f) * ppws[4 * k4 + 1]
                    + fmaxf(v.z, 0.f) * ppws[4 * k4 + 2]
                    + fmaxf(v.w, 0.f) * ppws[4 * k4 + 3];
            }
            out[gm] = 1.f / (1.f + expf(-(pp + ppb[0])));
            out[n + gm] = (t[gm] > 0) ? (y1s[tid] + b11[0]) : (y0s[tid] + b01[0]);
        }
    }
}

// ---------------------------------------------------------------------------
// CSR gather: warp per node, float4 lanes, 4-wide unroll (measured best;
// unroll-8 and 2-warp-split both measured worse).
// ---------------------------------------------------------------------------
__global__ __launch_bounds__(256) void gather_k(const float* __restrict__ h,
                                                const int* __restrict__ rowptr,
                                                const int* __restrict__ eidx,
                                                const float* __restrict__ ew,
                                                const float* __restrict__ dinv,
                                                const float* __restrict__ b,
                                                float* __restrict__ agg, int n) {
    const int lane = threadIdx.x & 31;
    const int node = (blockIdx.x * blockDim.x + threadIdx.x) >> 5;
    if (node >= n) return;

    const float4* h4 = (const float4*)h;
    float d = __ldg(dinv + node);
    float d2 = d * d;

    float4 sv = h4[(size_t)node * 32 + lane];
    float4 bb = ((const float4*)b)[lane];
    float4 a0, a1, a2, a3;
    a0.x = fmaf(sv.x, d2, bb.x); a0.y = fmaf(sv.y, d2, bb.y);
    a0.z = fmaf(sv.z, d2, bb.z); a0.w = fmaf(sv.w, d2, bb.w);
    a1 = make_float4(0.f, 0.f, 0.f, 0.f);
    a2 = make_float4(0.f, 0.f, 0.f, 0.f);
    a3 = make_float4(0.f, 0.f, 0.f, 0.f);

    int e = __ldg(rowptr + node);
    const int end = __ldg(rowptr + node + 1);
    for (; e + 3 < end; e += 4) {
        int r0 = __ldg(eidx + e),     r1 = __ldg(eidx + e + 1);
        int r2 = __ldg(eidx + e + 2), r3 = __ldg(eidx + e + 3);
        float w0 = __ldg(ew + e),     w1 = __ldg(ew + e + 1);
        float w2 = __ldg(ew + e + 2), w3 = __ldg(ew + e + 3);
        float4 v0 = h4[(size_t)r0 * 32 + lane];
        float4 v1 = h4[(size_t)r1 * 32 + lane];
        float4 v2 = h4[(size_t)r2 * 32 + lane];
        float4 v3 = h4[(size_t)r3 * 32 + lane];
        a0.x = fmaf(v0.x, w0, a0.x); a0.y = fmaf(v0.y, w0, a0.y);
        a0.z = fmaf(v0.z, w0, a0.z); a0.w = fmaf(v0.w, w0, a0.w);
        a1.x = fmaf(v1.x, w1, a1.x); a1.y = fmaf(v1.y, w1, a1.y);
        a1.z = fmaf(v1.z, w1, a1.z); a1.w = fmaf(v1.w, w1, a1.w);
        a2.x = fmaf(v2.x, w2, a2.x); a2.y = fmaf(v2.y, w2, a2.y);
        a2.z = fmaf(v2.z, w2, a2.z); a2.w = fmaf(v2.w, w2, a2.w);
        a3.x = fmaf(v3.x, w3, a3.x); a3.y = fmaf(v3.y, w3, a3.y);
        a3.z = fmaf(v3.z, w3, a3.z); a3.w = fmaf(v3.w, w3, a3.w);
    }
    for (; e < end; e++) {
        int r0 = __ldg(eidx + e);
        float w0 = __ldg(ew + e);
        float4 v0 = h4[(size_t)r0 * 32 + lane];
        a0.x = fmaf(v0.x, w0, a0.x); a0.y = fmaf(v0.y, w0, a0.y);
        a0.z = fmaf(v0.z, w0, a0.z); a0.w = fmaf(v0.w, w0, a0.w);
    }
    a0.x += a1.x + a2.x + a3.x;
    a0.y += a1.y + a2.y + a3.y;
    a0.z += a1.z + a2.z + a3.z;
    a0.w += a1.w + a2.w + a3.w;
    ((float4*)agg)[(size_t)node * 32 + lane] = a0;
}

// ---------------------------------------------------------------------------
extern "C" void kernel_launch(void* const* d_in, const int* in_sizes, int n_in,
                              void* d_out, int out_size) {
    const float* x   = (const float*)d_in[0];
    const int*   t   = (const int*)d_in[1];
    const int*   ei  = (const int*)d_in[3];
    const float* W0  = (const float*)d_in[4];
    const float* b0  = (const float*)d_in[5];
    const float* W1  = (const float*)d_in[6];
    const float* b1  = (const float*)d_in[7];
    const float* W00 = (const float*)d_in[8];
    const float* b00 = (const float*)d_in[9];
    const float* W10 = (const float*)d_in[10];
    const float* b10 = (const float*)d_in[11];
    const float* w01 = (const float*)d_in[12];
    const float* b01 = (const float*)d_in[13];
    const float* w11 = (const float*)d_in[14];
    const float* b11 = (const float*)d_in[15];
    const float* ppw = (const float*)d_in[16];
    const float* ppb = (const float*)d_in[17];
    float* out = (float*)d_out;

    const int N = in_sizes[0] / HID;
    const int E = in_sizes[3] / 2;
    const int* row = ei;
    const int* col = ei + E;

    float *h, *agg, *dinv, *ew;
    int *cnt, *rowptr, *cursor, *partial, *eidx;
    unsigned char* wimg;
    cudaGetSymbolAddress((void**)&h, g_h);
    cudaGetSymbolAddress((void**)&agg, g_agg);
    cudaGetSymbolAddress((void**)&dinv, g_dinv);
    cudaGetSymbolAddress((void**)&cnt, g_cnt);
    cudaGetSymbolAddress((void**)&rowptr, g_rowptr);
    cudaGetSymbolAddress((void**)&cursor, g_cursor);
    cudaGetSymbolAddress((void**)&partial, g_partial);
    cudaGetSymbolAddress((void**)&eidx, g_eidx);
    cudaGetSymbolAddress((void**)&ew, g_ew);
    cudaGetSymbolAddress((void**)&wimg, g_wimg);

    cudaFuncSetAttribute((const void*)mma_layer_k<false>,
                         cudaFuncAttributeMaxDynamicSharedMemorySize, SMEM_LAYER);
    cudaFuncSetAttribute((const void*)mma_layer_k<true>,
                         cudaFuncAttributeMaxDynamicSharedMemorySize, SMEM_LAYER);
    cudaFuncSetAttribute((const void*)mma_head_k,
                         cudaFuncAttributeMaxDynamicSharedMemorySize, SMEM_HEAD);

    // Side stream + events for forked capture (host-side objects, created
    // once; the captured graph has identical structure on every call).
    static cudaStream_t s2 = nullptr;
    static cudaEvent_t evFork = nullptr, evJoin = nullptr;
    if (s2 == nullptr) {
        cudaStreamCreateWithFlags(&s2, cudaStreamNonBlocking);
        cudaEventCreateWithFlags(&evFork, cudaEventDisableTiming);
        cudaEventCreateWithFlags(&evJoin, cudaEventDisableTiming);
    }

    const int nparts = (N + SCAN_B - 1) / SCAN_B;
    const int gb256 = (N + 255) / 256;
    const int gb128 = (N + 127) / 128;
    const int gg = (N * 32 + 255) / 256;

    // Fork: CSR build on s2; wsplit + layer-1 GEMM on the main stream.
    cudaEventRecord(evFork, 0);
    cudaStreamWaitEvent(s2, evFork, 0);

    cnt_zero_k<<<(N + 255) / 256, 256, 0, s2>>>(cnt, N);
    cnt_k<<<(E + 255) / 256, 256, 0, s2>>>(col, cnt, E);
    dinv_k<<<(N + 255) / 256, 256, 0, s2>>>(cnt, dinv, N);
    scan1_k<<<nparts, SCAN_B, 0, s2>>>(cnt, rowptr, partial, N);
    scan2_k<<<1, SCAN_B, 0, s2>>>(partial, nparts);
    scan3_k<<<(N + 255) / 256, 256, 0, s2>>>(rowptr, cursor, partial, N, E);
    place_k<<<(E + 255) / 256, 256, 0, s2>>>(row, col, dinv, cursor, eidx, ew, E);
    cudaEventRecord(evJoin, s2);

    wsplit_k<<<4, 256>>>(W0, W1, W00 + 128 * 128, W10 + 128 * 128, wimg);
    mma_layer_k<false><<<gb256, 512, SMEM_LAYER>>>(x, wimg, wimg + IMGB, h, N);

    // Join: gather needs the CSR.
    cudaStreamWaitEvent(0, evJoin, 0);
    gather_k<<<gg, 256>>>(h, rowptr, eidx, ew, dinv, b0, agg, N);

    mma_layer_k<true><<<gb256, 512, SMEM_LAYER>>>(agg, wimg + 2 * IMGB, wimg + 3 * IMGB, h, N);
    gather_k<<<gg, 256>>>(h, rowptr, eidx, ew, dinv, b1, agg, N);

    mma_head_k<<<gb128, 512, SMEM_HEAD>>>(agg, wimg + 4 * IMGB,
                                          b00 + 128, b10 + 128,
                                          w01, b01, w11, b11, ppw, ppb, t, out, N);
}